// round 3
// baseline (speedup 1.0000x reference)
#include <cuda_runtime.h>
#include <cstdint>

#define NB 2
#define NH 16
#define NS 2048
#define ND 128
#define PITCH 132                      // 128 + 4 floats pad: 528B row, conflict-free ldmatrix/STS

// tf32-converted, pre-scaled copies of q and k (scratch via __device__ globals; 64 MB total)
__device__ float g_qbuf[(size_t)NB * NH * NS * ND];
__device__ float g_kbuf[(size_t)NB * NH * NS * ND];

__device__ __forceinline__ uint32_t cvt_tf32(float x) {
    uint32_t r;
    asm("cvt.rna.tf32.f32 %0, %1;" : "=r"(r) : "f"(x));
    return r;
}

// ---------------------------------------------------------------------------
// Prepass: qbuf = rna_tf32(q * head_scale / sqrt(D)), kbuf = rna_tf32(k)
// ---------------------------------------------------------------------------
__global__ void prep_kernel(const float* __restrict__ q, const float* __restrict__ k,
                            const float* __restrict__ hs) {
    int idx = blockIdx.x * 256 + threadIdx.x;   // float4 index; S*D/4 = 65536 per (b,h)
    if (blockIdx.y == 0) {
        float4 v = ((const float4*)q)[idx];
        float s = hs[(idx >> 16) & (NH - 1)] * 0.08838834764831845f;  // 1/sqrt(128)
        float4 o;
        o.x = __uint_as_float(cvt_tf32(v.x * s));
        o.y = __uint_as_float(cvt_tf32(v.y * s));
        o.z = __uint_as_float(cvt_tf32(v.z * s));
        o.w = __uint_as_float(cvt_tf32(v.w * s));
        ((float4*)g_qbuf)[idx] = o;
    } else {
        float4 v = ((const float4*)k)[idx];
        float4 o;
        o.x = __uint_as_float(cvt_tf32(v.x));
        o.y = __uint_as_float(cvt_tf32(v.y));
        o.z = __uint_as_float(cvt_tf32(v.z));
        o.w = __uint_as_float(cvt_tf32(v.w));
        ((float4*)g_kbuf)[idx] = o;
    }
}

// ---------------------------------------------------------------------------
// PTX helpers
// ---------------------------------------------------------------------------
__device__ __forceinline__ void cp16(float* s, const float* g) {
    uint32_t sa = (uint32_t)__cvta_generic_to_shared(s);
    asm volatile("cp.async.cg.shared.global [%0], [%1], 16;" :: "r"(sa), "l"(g));
}

__device__ __forceinline__ void ldm4(uint32_t* d, uint32_t addr) {
    asm volatile("ldmatrix.sync.aligned.m8n8.x4.shared.b16 {%0,%1,%2,%3}, [%4];"
                 : "=r"(d[0]), "=r"(d[1]), "=r"(d[2]), "=r"(d[3]) : "r"(addr));
}

__device__ __forceinline__ void mma8(float* c, const uint32_t* a, uint32_t b0, uint32_t b1) {
    asm volatile("mma.sync.aligned.m16n8k8.row.col.f32.tf32.tf32.f32 "
                 "{%0,%1,%2,%3}, {%4,%5,%6,%7}, {%8,%9}, {%0,%1,%2,%3};"
                 : "+f"(c[0]), "+f"(c[1]), "+f"(c[2]), "+f"(c[3])
                 : "r"(a[0]), "r"(a[1]), "r"(a[2]), "r"(a[3]), "r"(b0), "r"(b1));
}

// ---------------------------------------------------------------------------
// Main kernel: per CTA, one 128-row Q tile x 8 K-tiles (double-buffered cp.async),
// fused separable ALiBi bias in the epilogue.
//   grid = (2 n-halves, 16 m-tiles, 32 bh), block = 256 (8 warps, 4m x 2n grid,
//   warp tile 32x64)
// ---------------------------------------------------------------------------
#define SMEM_FLOATS (3 * 128 * PITCH + 128 + 1024)
#define SMEM_BYTES  (SMEM_FLOATS * 4)

__global__ __launch_bounds__(256, 1)
void alibi_gemm(const float* __restrict__ slopes, const float* __restrict__ positions,
                const int* __restrict__ tok, float* __restrict__ out) {
    extern __shared__ float smem[];
    float* Qs  = smem;
    float* K0s = smem + 128 * PITCH;
    float* K1s = smem + 2 * 128 * PITCH;
    float* pq  = smem + 3 * 128 * PITCH;   // 128: slope*pos per query row
    float* pk  = pq + 128;                 // 1024: slope*pos per key col (8 tiles)

    const int tid  = threadIdx.x;
    const int lane = tid & 31;
    const int warp = tid >> 5;
    const int bh   = blockIdx.z;
    const int b    = bh >> 4;
    const int m0   = blockIdx.y * 128;
    const int nb   = blockIdx.x * 1024;
    const float slope = slopes[bh & 15];

    // bias vectors (separable ALiBi): a_i = slope*pos[tok[b,i]], b_j likewise
    if (tid < 128)
        pq[tid] = slope * positions[tok[b * NS + m0 + tid]];
    for (int i = tid; i < 1024; i += 256)
        pk[i] = slope * positions[tok[b * NS + nb + i]];

    const float* qsrc = g_qbuf + ((size_t)bh * NS + m0) * ND;
    const float* ksrc = g_kbuf + ((size_t)bh * NS + nb) * ND;

    // cp.async staging: each thread owns one 16B column (c4) and 16 rows
    const int c4  = (tid & 31) * 4;   // float offset within row
    const int r0w = tid >> 5;         // 0..7

    #pragma unroll
    for (int it = 0; it < 16; it++) {
        int row = r0w + it * 8;
        cp16(Qs + row * PITCH + c4, qsrc + row * ND + c4);
    }
    #pragma unroll
    for (int it = 0; it < 16; it++) {
        int row = r0w + it * 8;
        cp16(K0s + row * PITCH + c4, ksrc + row * ND + c4);
    }
    asm volatile("cp.async.commit_group;");          // G0 = {Q, K tile 0}
    #pragma unroll
    for (int it = 0; it < 16; it++) {
        int row = r0w + it * 8;
        cp16(K1s + row * PITCH + c4, ksrc + (size_t)(128 + row) * ND + c4);
    }
    asm volatile("cp.async.commit_group;");          // G1 = {K tile 1}

    const int warp_m = (warp >> 1) * 32;   // 0,32,64,96
    const int warp_n = (warp & 1) * 64;    // 0,64

    // ldmatrix base addresses (byte offsets; rows pitch 528B)
    const uint32_t a_base = (uint32_t)__cvta_generic_to_shared(
        Qs + (warp_m + (lane & 15)) * PITCH + ((lane >> 4) << 2));
    const uint32_t b_off = (uint32_t)(((warp_n + (lane & 7)) * PITCH + ((lane >> 3) << 2)) * 4);
    const uint32_t k0_base = (uint32_t)__cvta_generic_to_shared(K0s) + b_off;
    const uint32_t k1_base = (uint32_t)__cvta_generic_to_shared(K1s) + b_off;

    #pragma unroll 1
    for (int t = 0; t < 8; t++) {
        if (t == 7) asm volatile("cp.async.wait_group 0;");
        else        asm volatile("cp.async.wait_group 1;");
        __syncthreads();

        float acc[2][8][4];
        #pragma unroll
        for (int mi = 0; mi < 2; mi++)
            #pragma unroll
            for (int nf = 0; nf < 8; nf++)
                #pragma unroll
                for (int r = 0; r < 4; r++)
                    acc[mi][nf][r] = 0.0f;

        const uint32_t bb = (t & 1) ? k1_base : k0_base;

        #pragma unroll
        for (int ks2 = 0; ks2 < 8; ks2++) {          // two k8 steps per iter -> K=128
            uint32_t A[2][2][4];
            #pragma unroll
            for (int mi = 0; mi < 2; mi++)
                #pragma unroll
                for (int kk = 0; kk < 2; kk++)
                    ldm4(A[mi][kk], a_base + mi * (16 * PITCH * 4) + (ks2 * 2 + kk) * 32);
            #pragma unroll
            for (int nf = 0; nf < 8; nf++) {
                uint32_t Bv[4];                      // b0,b1 of kstep even; b0,b1 of kstep odd
                ldm4(Bv, bb + nf * (8 * PITCH * 4) + ks2 * 64);
                #pragma unroll
                for (int mi = 0; mi < 2; mi++) {
                    mma8(acc[mi][nf], A[mi][0], Bv[0], Bv[1]);
                    mma8(acc[mi][nf], A[mi][1], Bv[2], Bv[3]);
                }
            }
        }

        // epilogue: out = scores - a_i + b_j, float2 stores
        const int n0 = nb + t * 128;
        const float* pkt = pk + t * 128;
        #pragma unroll
        for (int mi = 0; mi < 2; mi++) {
            const int r = warp_m + mi * 16 + (lane >> 2);
            const float pq0 = pq[r], pq1 = pq[r + 8];
            float* orow = out + ((size_t)bh * NS + m0 + r) * NS + n0;
            #pragma unroll
            for (int nf = 0; nf < 8; nf++) {
                const int c = warp_n + nf * 8 + ((lane & 3) << 1);
                const float pk0 = pkt[c], pk1 = pkt[c + 1];
                float2 v0 = make_float2(acc[mi][nf][0] + (pk0 - pq0),
                                        acc[mi][nf][1] + (pk1 - pq0));
                float2 v1 = make_float2(acc[mi][nf][2] + (pk0 - pq1),
                                        acc[mi][nf][3] + (pk1 - pq1));
                *(float2*)(orow + c)                   = v0;
                *(float2*)(orow + (size_t)8 * NS + c)  = v1;
            }
        }

        __syncthreads();   // everyone done reading buf (t&1) before overwriting it
        if (t + 2 < 8) {
            const float* src = ksrc + (size_t)(t + 2) * 128 * ND;
            float* dstb = (t & 1) ? K1s : K0s;
            #pragma unroll
            for (int it = 0; it < 16; it++) {
                int row = r0w + it * 8;
                cp16(dstb + row * PITCH + c4, src + row * ND + c4);
            }
            asm volatile("cp.async.commit_group;");
        }
    }
}

// ---------------------------------------------------------------------------
// Launch
// ---------------------------------------------------------------------------
extern "C" void kernel_launch(void* const* d_in, const int* in_sizes, int n_in,
                              void* d_out, int out_size) {
    const float* q           = (const float*)d_in[0];
    const float* k           = (const float*)d_in[1];
    const float* head_scales = (const float*)d_in[2];
    const float* slopes      = (const float*)d_in[3];
    const float* positions   = (const float*)d_in[4];
    const int*   tok         = (const int*)d_in[5];
    float*       out         = (float*)d_out;

    // 8.39M floats per tensor -> 2.097M float4 -> exactly 8192 blocks of 256
    prep_kernel<<<dim3(8192, 2), 256>>>(q, k, head_scales);

    cudaFuncSetAttribute(alibi_gemm, cudaFuncAttributeMaxDynamicSharedMemorySize, SMEM_BYTES);
    alibi_gemm<<<dim3(2, 16, 32), 256, SMEM_BYTES>>>(slopes, positions, tok, out);
}

// round 5
// speedup vs baseline: 1.6018x; 1.6018x over previous
#include <cuda_runtime.h>
#include <cuda_bf16.h>
#include <cstdint>

#define NB 2
#define NH 16
#define NS 2048
#define ND 128
#define PITCH 136          // bf16 elems per smem row: 272 B, conflict-free ldmatrix

// bf16 scratch (q pre-scaled by head_scale/sqrt(D)), row-major [bh][s][d]
__device__ __align__(16) __nv_bfloat16 g_qb[(size_t)NB * NH * NS * ND];
__device__ __align__(16) __nv_bfloat16 g_kb[(size_t)NB * NH * NS * ND];

__device__ __forceinline__ uint32_t pack2(float a, float b) {
    __nv_bfloat162 h = __floats2bfloat162_rn(a, b);
    return *(uint32_t*)&h;
}

// ---------------------------------------------------------------------------
// Prepass: fp32 -> bf16, q scaled per head
// ---------------------------------------------------------------------------
__global__ void prep_kernel(const float* __restrict__ q, const float* __restrict__ k,
                            const float* __restrict__ hs) {
    size_t e = ((size_t)blockIdx.x * 256 + threadIdx.x) * 8;
    if (blockIdx.y == 0) {
        float4 v0 = ((const float4*)(q + e))[0];
        float4 v1 = ((const float4*)(q + e))[1];
        float sc = hs[(e >> 18) & (NH - 1)] * 0.08838834764831845f;   // 1/sqrt(128)
        uint4 w;
        w.x = pack2(v0.x * sc, v0.y * sc);
        w.y = pack2(v0.z * sc, v0.w * sc);
        w.z = pack2(v1.x * sc, v1.y * sc);
        w.w = pack2(v1.z * sc, v1.w * sc);
        *(uint4*)(g_qb + e) = w;
    } else {
        float4 v0 = ((const float4*)(k + e))[0];
        float4 v1 = ((const float4*)(k + e))[1];
        uint4 w;
        w.x = pack2(v0.x, v0.y);
        w.y = pack2(v0.z, v0.w);
        w.z = pack2(v1.x, v1.y);
        w.w = pack2(v1.z, v1.w);
        *(uint4*)(g_kb + e) = w;
    }
}

// ---------------------------------------------------------------------------
// PTX helpers
// ---------------------------------------------------------------------------
__device__ __forceinline__ void cp16(uint32_t saddr, const void* g) {
    asm volatile("cp.async.cg.shared.global [%0], [%1], 16;" :: "r"(saddr), "l"(g));
}

__device__ __forceinline__ void ldm4(uint32_t* d, uint32_t addr) {
    asm volatile("ldmatrix.sync.aligned.m8n8.x4.shared.b16 {%0,%1,%2,%3}, [%4];"
                 : "=r"(d[0]), "=r"(d[1]), "=r"(d[2]), "=r"(d[3]) : "r"(addr));
}

__device__ __forceinline__ void mma16(float* c, const uint32_t* a, uint32_t b0, uint32_t b1) {
    asm volatile("mma.sync.aligned.m16n8k16.row.col.f32.bf16.bf16.f32 "
                 "{%0,%1,%2,%3}, {%4,%5,%6,%7}, {%8,%9}, {%0,%1,%2,%3};"
                 : "+f"(c[0]), "+f"(c[1]), "+f"(c[2]), "+f"(c[3])
                 : "r"(a[0]), "r"(a[1]), "r"(a[2]), "r"(a[3]), "r"(b0), "r"(b1));
}

// SMEM byte offsets (bf16 tiles, 272 B rows)
#define TILE_B   (128 * PITCH * 2)          // 34816
#define Q_OFF    0
#define K0_OFF   TILE_B
#define K1_OFF   (2 * TILE_B)
#define PQ_OFF   (3 * TILE_B)               // 104448
#define PK_OFF   (PQ_OFF + 512)
#define SMEM_BYTES (PK_OFF + 4096)          // 109056 -> 2 CTAs/SM

// ---------------------------------------------------------------------------
// Main: per CTA one 128-row Q tile x 8 K-tiles (double-buffered cp.async),
// bf16 m16n8k16 mma, fused separable ALiBi epilogue.
//   grid = (2 n-halves, 16 m-tiles, 32 bh), 256 threads, 2 CTAs/SM
// ---------------------------------------------------------------------------
__global__ __launch_bounds__(256, 2)
void alibi_gemm(const float* __restrict__ slopes, const float* __restrict__ positions,
                const int* __restrict__ tok, float* __restrict__ out) {
    extern __shared__ unsigned char smem[];
    const uint32_t sbase = (uint32_t)__cvta_generic_to_shared(smem);
    float* pq = (float*)(smem + PQ_OFF);
    float* pk = (float*)(smem + PK_OFF);

    const int tid  = threadIdx.x;
    const int lane = tid & 31;
    const int warp = tid >> 5;
    const int bh   = blockIdx.z;
    const int b    = bh >> 4;
    const int m0   = blockIdx.y * 128;
    const int nb   = blockIdx.x * 1024;
    const float slope = slopes[bh & 15];

    // separable ALiBi bias vectors
    if (tid < 128)
        pq[tid] = slope * positions[tok[b * NS + m0 + tid]];
    for (int i = tid; i < 1024; i += 256)
        pk[i] = slope * positions[tok[b * NS + nb + i]];

    const __nv_bfloat16* qsrc = g_qb + ((size_t)bh * NS + m0) * ND;
    const __nv_bfloat16* ksrc = g_kb + ((size_t)bh * NS + nb) * ND;

    // tile = 128 rows x 256 B = 2048 x 16B chunks; thread owns 8 chunks
    #pragma unroll
    for (int i = 0; i < 8; i++) {
        int c = tid + i * 256, row = c >> 4, col = c & 15;
        cp16(sbase + Q_OFF + row * 272 + col * 16, (const char*)qsrc + row * 256 + col * 16);
    }
    #pragma unroll
    for (int i = 0; i < 8; i++) {
        int c = tid + i * 256, row = c >> 4, col = c & 15;
        cp16(sbase + K0_OFF + row * 272 + col * 16, (const char*)ksrc + row * 256 + col * 16);
    }
    asm volatile("cp.async.commit_group;");          // G0 = {Q, K0}
    #pragma unroll
    for (int i = 0; i < 8; i++) {
        int c = tid + i * 256, row = c >> 4, col = c & 15;
        cp16(sbase + K1_OFF + row * 272 + col * 16,
             (const char*)ksrc + (128 + row) * 256 + col * 16);
    }
    asm volatile("cp.async.commit_group;");          // G1 = {K1}

    const int warp_m = (warp >> 1) * 32;   // 0,32,64,96
    const int warp_n = (warp & 1) * 64;    // 0,64

    // ldmatrix bases (byte offsets, rows 272 B)
    // A x4: lanes 0-15 -> rows m..m+15 colbyte 0; lanes 16-31 -> same rows colbyte 16
    const uint32_t a_base = sbase + Q_OFF
        + (uint32_t)((warp_m + (lane & 15)) * 272 + (lane >> 4) * 16);
    // B x4 group g: rows warp_n + g*16 + (lane&15), colbyte (lane>>4)*16
    const uint32_t b_off = (uint32_t)((warp_n + (lane & 15)) * 272 + (lane >> 4) * 16);
    const uint32_t k0_base = sbase + K0_OFF + b_off;
    const uint32_t k1_base = sbase + K1_OFF + b_off;

    #pragma unroll 1
    for (int t = 0; t < 8; t++) {
        if (t == 7) asm volatile("cp.async.wait_group 0;");
        else        asm volatile("cp.async.wait_group 1;");
        __syncthreads();

        float acc[2][8][4];
        #pragma unroll
        for (int mi = 0; mi < 2; mi++)
            #pragma unroll
            for (int nf = 0; nf < 8; nf++)
                #pragma unroll
                for (int r = 0; r < 4; r++)
                    acc[mi][nf][r] = 0.0f;

        const uint32_t bb = (t & 1) ? k1_base : k0_base;

        #pragma unroll
        for (int ks = 0; ks < 8; ks++) {             // k16 steps -> K=128
            uint32_t A[2][4];
            ldm4(A[0], a_base + ks * 32);
            ldm4(A[1], a_base + ks * 32 + 16 * 272);
            #pragma unroll
            for (int g = 0; g < 4; g++) {            // two n8 frags per group
                uint32_t Bv[4];
                ldm4(Bv, bb + g * (16 * 272) + ks * 32);
                // Bv: r0=b0(nf=2g) r1=b0(nf=2g+1) r2=b1(nf=2g) r3=b1(nf=2g+1)
                mma16(acc[0][2 * g],     A[0], Bv[0], Bv[2]);
                mma16(acc[0][2 * g + 1], A[0], Bv[1], Bv[3]);
                mma16(acc[1][2 * g],     A[1], Bv[0], Bv[2]);
                mma16(acc[1][2 * g + 1], A[1], Bv[1], Bv[3]);
            }
        }

        // epilogue: out = scores - a_i + b_j
        const int n0 = nb + t * 128;
        const float* pkt = pk + t * 128;
        #pragma unroll
        for (int mi = 0; mi < 2; mi++) {
            const int r = warp_m + mi * 16 + (lane >> 2);
            const float pq0 = pq[r], pq1 = pq[r + 8];
            float* orow = out + ((size_t)bh * NS + m0 + r) * NS + n0;
            #pragma unroll
            for (int nf = 0; nf < 8; nf++) {
                const int c = warp_n + nf * 8 + ((lane & 3) << 1);
                const float pk0 = pkt[c], pk1 = pkt[c + 1];
                float2 v0 = make_float2(acc[mi][nf][0] + (pk0 - pq0),
                                        acc[mi][nf][1] + (pk1 - pq0));
                float2 v1 = make_float2(acc[mi][nf][2] + (pk0 - pq1),
                                        acc[mi][nf][3] + (pk1 - pq1));
                *(float2*)(orow + c)                  = v0;
                *(float2*)(orow + (size_t)8 * NS + c) = v1;
            }
        }

        __syncthreads();   // all reads of buf (t&1) done before refill
        if (t + 2 < 8) {
            const char* src = (const char*)ksrc + (size_t)(t + 2) * 128 * 256;
            uint32_t dstb = sbase + ((t & 1) ? K1_OFF : K0_OFF);
            #pragma unroll
            for (int i = 0; i < 8; i++) {
                int c = tid + i * 256, row = c >> 4, col = c & 15;
                cp16(dstb + row * 272 + col * 16, src + row * 256 + col * 16);
            }
            asm volatile("cp.async.commit_group;");
        }
    }
}

// ---------------------------------------------------------------------------
// Launch
// ---------------------------------------------------------------------------
extern "C" void kernel_launch(void* const* d_in, const int* in_sizes, int n_in,
                              void* d_out, int out_size) {
    const float* q           = (const float*)d_in[0];
    const float* k           = (const float*)d_in[1];
    const float* head_scales = (const float*)d_in[2];
    const float* slopes      = (const float*)d_in[3];
    const float* positions   = (const float*)d_in[4];
    const int*   tok         = (const int*)d_in[5];
    float*       out         = (float*)d_out;

    // 8.39M floats per tensor / 8 per thread = 1.048M threads = 4096 blocks x 256
    prep_kernel<<<dim3(4096, 2), 256>>>(q, k, head_scales);

    cudaFuncSetAttribute(alibi_gemm, cudaFuncAttributeMaxDynamicSharedMemorySize, SMEM_BYTES);
    alibi_gemm<<<dim3(2, 16, 32), 256, SMEM_BYTES>>>(slopes, positions, tok, out);
}